// round 2
// baseline (speedup 1.0000x reference)
#include <cuda_runtime.h>
#include <cstdint>

// ---------------------------------------------------------------------------
// Problem: z = z_roi @ w_emb + b   [2048 x 65536] @ [65536 x 256]
//          z_all = mask ? z : 0
//          s = mask ? student_t(z, centroids) : 0   (alpha = 1 -> 1/(1+dist))
//          c = argmax_k s
// Output layout: [z_all (M*NDF) | s (M*K) | c (M)] all float32.
// mask arrives as int32 (bool promoted by the harness).
// ---------------------------------------------------------------------------

#define TM 32
#define TN 128
#define TK 32

__global__ __launch_bounds__(256) void emb_gemm_kernel(
    const float* __restrict__ A,            // [M, Kdim]
    const float* __restrict__ B,            // [Kdim, N]
    const float* __restrict__ bias,         // [N]
    const int* __restrict__ mask,           // [M] (int32 bool)
    float* __restrict__ C,                  // [M, N]
    int M, int Kdim, int N)
{
    __shared__ float As[TK][TM + 1];                 // transposed, +1 pad
    __shared__ __align__(16) float Bs[TK][TN];

    const int tid = threadIdx.x;
    const int block_m = blockIdx.x * TM;
    const int block_n = blockIdx.y * TN;

    const int tx = tid & 31;   // 0..31 -> 4-col group
    const int ty = tid >> 5;   // 0..7  -> 4-row group

    // A tile load map: one float4 per thread (32x32 tile = 256 float4)
    const int a_row = tid >> 3;          // 0..31
    const int a_col = (tid & 7) << 2;    // 0,4,...,28
    // B tile load map: four float4 per thread (32x128 tile)
    const int b_col  = (tid & 31) << 2;  // 0..124
    const int b_row0 = tid >> 5;         // 0..7

    const float* Ap = A + (size_t)(block_m + a_row) * Kdim + a_col;
    const float* Bp = B + block_n + b_col;

    float acc[4][4];
    #pragma unroll
    for (int i = 0; i < 4; i++)
        #pragma unroll
        for (int j = 0; j < 4; j++)
            acc[i][j] = 0.0f;

    // prefetch first tiles into registers
    float4 a_reg = *reinterpret_cast<const float4*>(Ap);
    float4 b_reg[4];
    #pragma unroll
    for (int i = 0; i < 4; i++)
        b_reg[i] = *reinterpret_cast<const float4*>(Bp + (size_t)(b_row0 + 8 * i) * N);

    for (int k0 = 0; k0 < Kdim; k0 += TK) {
        // registers -> shared
        As[a_col + 0][a_row] = a_reg.x;
        As[a_col + 1][a_row] = a_reg.y;
        As[a_col + 2][a_row] = a_reg.z;
        As[a_col + 3][a_row] = a_reg.w;
        #pragma unroll
        for (int i = 0; i < 4; i++)
            *reinterpret_cast<float4*>(&Bs[b_row0 + 8 * i][b_col]) = b_reg[i];
        __syncthreads();

        // prefetch next tiles (latency hidden by the compute below)
        if (k0 + TK < Kdim) {
            a_reg = *reinterpret_cast<const float4*>(Ap + k0 + TK);
            #pragma unroll
            for (int i = 0; i < 4; i++)
                b_reg[i] = *reinterpret_cast<const float4*>(
                    Bp + (size_t)(k0 + TK + b_row0 + 8 * i) * N);
        }

        #pragma unroll
        for (int k = 0; k < TK; k++) {
            float a0 = As[k][(ty << 2) + 0];
            float a1 = As[k][(ty << 2) + 1];
            float a2 = As[k][(ty << 2) + 2];
            float a3 = As[k][(ty << 2) + 3];
            float4 bv = *reinterpret_cast<const float4*>(&Bs[k][tx << 2]);
            acc[0][0] += a0 * bv.x; acc[0][1] += a0 * bv.y;
            acc[0][2] += a0 * bv.z; acc[0][3] += a0 * bv.w;
            acc[1][0] += a1 * bv.x; acc[1][1] += a1 * bv.y;
            acc[1][2] += a1 * bv.z; acc[1][3] += a1 * bv.w;
            acc[2][0] += a2 * bv.x; acc[2][1] += a2 * bv.y;
            acc[2][2] += a2 * bv.z; acc[2][3] += a2 * bv.w;
            acc[3][0] += a3 * bv.x; acc[3][1] += a3 * bv.y;
            acc[3][2] += a3 * bv.z; acc[3][3] += a3 * bv.w;
        }
        __syncthreads();
    }

    // epilogue: bias + mask, vectorized store
    #pragma unroll
    for (int i = 0; i < 4; i++) {
        const int row = block_m + (ty << 2) + i;
        const float mval = mask[row] ? 1.0f : 0.0f;
        const int col = block_n + (tx << 2);
        float4 ov;
        ov.x = (acc[i][0] + bias[col + 0]) * mval;
        ov.y = (acc[i][1] + bias[col + 1]) * mval;
        ov.z = (acc[i][2] + bias[col + 2]) * mval;
        ov.w = (acc[i][3] + bias[col + 3]) * mval;
        *reinterpret_cast<float4*>(&C[(size_t)row * N + col]) = ov;
    }
}

// ---------------------------------------------------------------------------
// Per-row student-t + normalize + argmax. One block per (b, s) row.
// K <= 128, NDF multiple of 4.
// ---------------------------------------------------------------------------
__global__ __launch_bounds__(128) void cluster_kernel(
    const float* __restrict__ Z,            // [M, NDF] (already masked)
    const float* __restrict__ cent,         // [K, NDF]
    const int* __restrict__ mask,           // [M] (int32 bool)
    float* __restrict__ S,                  // [M, K]
    float* __restrict__ Cidx,               // [M]
    int NDF, int K)
{
    const int row = blockIdx.x;
    const int tid = threadIdx.x;

    __shared__ __align__(16) float zs[256];
    __shared__ float stmp[128];
    __shared__ float red_sum;
    __shared__ int   red_idx;

    for (int i = tid; i < NDF; i += blockDim.x)
        zs[i] = Z[(size_t)row * NDF + i];
    __syncthreads();

    float val = 0.0f;
    if (tid < K) {
        const float4* c4 = reinterpret_cast<const float4*>(cent + (size_t)tid * NDF);
        const float4* z4 = reinterpret_cast<const float4*>(zs);
        float d2 = 0.0f;
        #pragma unroll 8
        for (int j = 0; j < NDF / 4; j++) {
            float4 cv = c4[j];
            float4 zv = z4[j];
            float dx = zv.x - cv.x;
            float dy = zv.y - cv.y;
            float dz = zv.z - cv.z;
            float dw = zv.w - cv.w;
            d2 += dx * dx + dy * dy + dz * dz + dw * dw;
        }
        float dist = sqrtf(fmaxf(d2, 0.0f));
        // alpha = 1: (1 + dist)^(-(1+1)/2) = 1/(1+dist)
        val = 1.0f / (1.0f + dist);
    }
    stmp[tid] = val;
    __syncthreads();

    // warp 0 reduces sum and argmax (first max index, matching jnp.argmax)
    if (tid < 32) {
        float sum = 0.0f;
        float best = -1.0f;
        int bidx = 0;
        for (int k = tid; k < K; k += 32) {
            float v = stmp[k];
            sum += v;
            if (v > best) { best = v; bidx = k; }
        }
        #pragma unroll
        for (int off = 16; off > 0; off >>= 1) {
            sum += __shfl_down_sync(0xffffffffu, sum, off);
            float ob = __shfl_down_sync(0xffffffffu, best, off);
            int   oi = __shfl_down_sync(0xffffffffu, bidx, off);
            if (ob > best || (ob == best && oi < bidx)) { best = ob; bidx = oi; }
        }
        if (tid == 0) { red_sum = sum; red_idx = bidx; }
    }
    __syncthreads();

    const bool mrow = mask[row] != 0;
    const float inv = mrow ? (1.0f / red_sum) : 0.0f;
    if (tid < K)
        S[(size_t)row * K + tid] = val * inv;
    if (tid == 0)
        Cidx[row] = mrow ? (float)red_idx : 0.0f;
}

// ---------------------------------------------------------------------------
extern "C" void kernel_launch(void* const* d_in, const int* in_sizes, int n_in,
                              void* d_out, int out_size)
{
    const float* z_roi = (const float*)d_in[0];   // [M, Kdim]
    const int*   mask  = (const int*)d_in[1];     // [M] bool -> int32
    const float* w_emb = (const float*)d_in[2];   // [Kdim, NDF]
    const float* b_emb = (const float*)d_in[3];   // [NDF]
    const float* cent  = (const float*)d_in[4];   // [K, NDF]

    const int M    = in_sizes[1];            // 2048 (= BN*SN)
    const int Kdim = in_sizes[0] / M;        // 65536
    const int NDF  = in_sizes[3];            // 256
    const int NC   = in_sizes[4] / NDF;      // 100

    float* out  = (float*)d_out;
    float* zall = out;                                   // [M, NDF]
    float* S    = out + (size_t)M * NDF;                 // [M, NC]
    float* Cx   = S + (size_t)M * NC;                    // [M]

    dim3 grid(M / TM, NDF / TN);
    emb_gemm_kernel<<<grid, 256>>>(z_roi, w_emb, b_emb, mask, zall, M, Kdim, NDF);
    cluster_kernel<<<M, 128>>>(zall, cent, mask, S, Cx, NDF, NC);
}